// round 7
// baseline (speedup 1.0000x reference)
#include <cuda_runtime.h>
#include <cstdint>

// out[b, 0:128]   = emb[idx[b], :]    (128 f32)
// out[b, 128:146] = genre[idx[b], :]  (18 f32)
// idx is int32 (JAX downcasts int64 without x64).
//
// Warp handles 4 consecutive rows (one int4 idx broadcast -> 4 independent
// emb gathers + 4 predicated genre gathers in flight; MLP ~= 8).
// Cache policy split:
//   - table gathers: ld.global.nc.L2::cache_hint with a
//     createpolicy.fractional.L2::evict_last policy (pin 58 MB tables in L2)
//   - output stores: __stcs (evict-first streaming, 612 MB write stream)
//   - idx loads:     __ldcs (read-once)

#define ROWS_PER_WARP 4

__device__ __forceinline__ uint64_t mk_evict_last_policy() {
    uint64_t pol;
    asm volatile("createpolicy.fractional.L2::evict_last.b64 %0, 1.0;" : "=l"(pol));
    return pol;
}
__device__ __forceinline__ float4 ldg_el4(const float4* p, uint64_t pol) {
    float4 v;
    asm volatile("ld.global.nc.L2::cache_hint.v4.f32 {%0,%1,%2,%3}, [%4], %5;"
                 : "=f"(v.x), "=f"(v.y), "=f"(v.z), "=f"(v.w) : "l"(p), "l"(pol));
    return v;
}
__device__ __forceinline__ float2 ldg_el2(const float2* p, uint64_t pol) {
    float2 v;
    asm volatile("ld.global.nc.L2::cache_hint.v2.f32 {%0,%1}, [%2], %3;"
                 : "=f"(v.x), "=f"(v.y) : "l"(p), "l"(pol));
    return v;
}

__global__ void __launch_bounds__(256)
item_gather_concat_kernel(const int*    __restrict__ idx,
                          const float4* __restrict__ emb,   // [N, 32] float4
                          const float2* __restrict__ gen,   // [N, 9]  float2
                          float2*       __restrict__ out,   // [B, 73] float2
                          int B)
{
    const int lane  = threadIdx.x & 31;
    const int gwarp = (int)((blockIdx.x * (unsigned)blockDim.x + threadIdx.x) >> 5);
    const int r0    = gwarp * ROWS_PER_WARP;

    const uint64_t pol = mk_evict_last_policy();

    if (r0 + ROWS_PER_WARP <= B) {
        int4 iv = __ldcs((const int4*)(idx + r0));   // read-once broadcast
        int items[4] = {iv.x, iv.y, iv.z, iv.w};

        // Issue all independent gathers first (MLP), then store.
        float4 e[4];
        float2 g[4];
        #pragma unroll
        for (int j = 0; j < 4; j++)
            e[j] = ldg_el4(&emb[(size_t)items[j] * 32 + lane], pol);
        #pragma unroll
        for (int j = 0; j < 4; j++)
            if (lane < 9)
                g[j] = ldg_el2(&gen[(size_t)items[j] * 9 + lane], pol);

        #pragma unroll
        for (int j = 0; j < 4; j++) {
            float2* o = out + (size_t)(r0 + j) * 73;   // 8B-aligned rows
            __stcs(&o[lane * 2 + 0], make_float2(e[j].x, e[j].y));
            __stcs(&o[lane * 2 + 1], make_float2(e[j].z, e[j].w));
            if (lane < 9)
                __stcs(&o[64 + lane], g[j]);
        }
    } else {
        // Tail fallback (unused for B = 1M): one row at a time.
        for (int r = r0; r < B && r < r0 + ROWS_PER_WARP; r++) {
            int item = idx[r];
            float4 e = __ldg(&emb[(size_t)item * 32 + lane]);
            float2* o = out + (size_t)r * 73;
            o[lane * 2 + 0] = make_float2(e.x, e.y);
            o[lane * 2 + 1] = make_float2(e.z, e.w);
            if (lane < 9)
                o[64 + lane] = __ldg(&gen[(size_t)item * 9 + lane]);
        }
    }
}

extern "C" void kernel_launch(void* const* d_in, const int* in_sizes, int n_in,
                              void* d_out, int out_size)
{
    const int*    idx = (const int*)   d_in[0];
    const float4* emb = (const float4*)d_in[1];
    const float2* gen = (const float2*)d_in[2];
    float2*       out = (float2*)d_out;

    int B = in_sizes[0];                                   // 1048576
    int rowsPerBlock = 8 * ROWS_PER_WARP;                  // 8 warps/block
    int blocks = (B + rowsPerBlock - 1) / rowsPerBlock;    // 32768

    item_gather_concat_kernel<<<blocks, 256>>>(idx, emb, gen, out, B);
}